// round 17
// baseline (speedup 1.0000x reference)
#include <cuda_runtime.h>
#include <cuda_fp16.h>
#include <cstdint>

// ---------------------------------------------------------------------------
// Problem constants
// ---------------------------------------------------------------------------
#define M_DIM 4096
#define N_DIM 11008
#define K_DIM 4096
#define GROUP 128

#define BM 128            // CTA M tile
#define BN 256            // CTA N tile
#define KC 64             // K halves per pipeline chunk (= 128 bytes per row)
#define NKC (K_DIM / KC)  // 64 chunks
#define NMT (M_DIM / BM)  // 32
#define NNT (N_DIM / BN)  // 43

#define A_BLK_BYTES (BM * 128)       // 16384
#define B_BLK_BYTES (BN * 128)       // 32768
#define STAGE_BYTES (A_BLK_BYTES + B_BLK_BYTES)  // 49152
#define NSTAGES 4
#define SM_TOTAL (2048 + NSTAGES * STAGE_BYTES)  // 198656

// Tail: 1332 full tiles (9 exact waves of 148) + last 44 tiles K-split 3-way
// at FULL N (22+21+21 chunks) -> 132 pieces, ONE wave of 0.344 tile-units.
#define FULL_CTAS 1332
#define TAIL_PIECES 132
#define GRID_CTAS (FULL_CTAS + TAIL_PIECES)   // 1464

// Merged prep: 22016 dequant + 8192 transform blocks (period-59 interleave),
// plus 1408 blocks zeroing the tail region of C (for the atomic epilogue).
#define DQ_BLOCKS 22016
#define TX_BLOCKS 8192
#define PREP_BLOCKS (DQ_BLOCKS + TX_BLOCKS)   // 30208
#define ZERO_BLOCKS 1408
#define PREP_TOTAL (PREP_BLOCKS + ZERO_BLOCKS)

// Tiled+swizzled scratch in GMEM
__device__ uint4 g_A[(size_t)NMT * NKC * A_BLK_BYTES / 16];   // 33.5 MB
__device__ uint4 g_B[(size_t)NNT * NKC * B_BLK_BYTES / 16];   // 90.2 MB

__host__ __device__ __forceinline__ uint32_t swz128(uint32_t off) {
    return off ^ ((off >> 3) & 0x70u);
}

// ---------------------------------------------------------------------------
// PTX helpers (sm_90-level only; tcgen05 NOT available in this build path)
// ---------------------------------------------------------------------------
__device__ __forceinline__ uint32_t smem_u32(const void* p) {
    uint32_t a;
    asm("{ .reg .u64 t; cvta.to.shared.u64 t, %1; cvt.u32.u64 %0, t; }" : "=r"(a) : "l"(p));
    return a;
}

#define MBAR_INIT(addr, cnt) \
    asm volatile("mbarrier.init.shared.b64 [%0], %1;" :: "r"(addr), "r"(cnt) : "memory")

#define MBAR_EXPECT_TX(addr, bytes) \
    asm volatile("mbarrier.arrive.expect_tx.shared.b64 _, [%0], %1;" :: "r"(addr), "r"(bytes) : "memory")

#define MBAR_ARRIVE(addr) \
    asm volatile("mbarrier.arrive.shared.b64 _, [%0];" :: "r"(addr) : "memory")

#define MBAR_WAIT(addr, parity) do {                                        \
    uint32_t _m = (addr); uint32_t _p = (parity); uint32_t _d;              \
    asm volatile("{\n\t.reg .pred p;\n\t"                                   \
        "mbarrier.try_wait.parity.acquire.cta.shared::cta.b64 p, [%1], %2;\n\t" \
        "selp.b32 %0, 1, 0, p;\n\t}"                                        \
        : "=r"(_d) : "r"(_m), "r"(_p) : "memory");                          \
    if (!_d) {                                                              \
        asm volatile("{\n\t.reg .pred P1;\n\t"                              \
            "W0_%=:\n\t"                                                    \
            "mbarrier.try_wait.parity.acquire.cta.shared::cta.b64 P1, [%0], %1, 0x989680;\n\t" \
            "@P1 bra.uni W1_%=;\n\t"                                        \
            "bra.uni W0_%=;\n\t"                                            \
            "W1_%=:\n\t}" :: "r"(_m), "r"(_p) : "memory");                  \
    }                                                                       \
} while (0)

__device__ __forceinline__ void bulk_ld(uint32_t dst, const void* src, uint32_t bytes,
                                        uint32_t mbar) {
    asm volatile(
        "cp.async.bulk.shared::cluster.global.mbarrier::complete_tx::bytes [%0], [%1], %2, [%3];"
        :: "r"(dst), "l"(src), "r"(bytes), "r"(mbar) : "memory");
}

__device__ __forceinline__ void ldsm4(uint32_t* r, uint32_t addr) {
    asm volatile("ldmatrix.sync.aligned.m8n8.x4.shared.b16 {%0,%1,%2,%3}, [%4];\n"
                 : "=r"(r[0]), "=r"(r[1]), "=r"(r[2]), "=r"(r[3]) : "r"(addr));
}
__device__ __forceinline__ void mma16816(float* c, const uint32_t* a, uint32_t b0, uint32_t b1) {
    asm volatile(
        "mma.sync.aligned.m16n8k16.row.col.f32.f16.f16.f32 "
        "{%0,%1,%2,%3}, {%4,%5,%6,%7}, {%8,%9}, {%0,%1,%2,%3};\n"
        : "+f"(c[0]), "+f"(c[1]), "+f"(c[2]), "+f"(c[3])
        : "r"(a[0]), "r"(a[1]), "r"(a[2]), "r"(a[3]), "r"(b0), "r"(b1));
}

// ---------------------------------------------------------------------------
// Kernel 1 (merged prep): period-59 interleaved dequant/transform (R16 form),
// plus ZERO_BLOCKS blocks that zero the tail region of C.
// ---------------------------------------------------------------------------
__global__ __launch_bounds__(256) void prep_kernel(
    const float* __restrict__ x, const float* __restrict__ s1,
    const float* __restrict__ s2, unsigned char* __restrict__ At,
    const uint4* __restrict__ pw4, const float* __restrict__ norms,
    const float* __restrict__ cent, unsigned char* __restrict__ Bt,
    float* __restrict__ out) {
    if (blockIdx.x >= PREP_BLOCKS) {
        // ---------------- zero C tail region (for atomic K-split epilogue) ----
        const int zb = blockIdx.x - PREP_BLOCKS;
        float4 z = {0.f, 0.f, 0.f, 0.f};
        float4* C4 = (float4*)out;
        if (zb < 1376) {
            // mt=31 row block: rows 3968..4095, all 11008 cols = 352256 float4
            const size_t f = (size_t)zb * 256 + threadIdx.x;
            C4[(size_t)3968 * 2752 + f] = z;
        } else {
            // tile (mt=30, nt=42): rows 3840..3967, cols 10752..11007
            const int f = (zb - 1376) * 256 + threadIdx.x;   // 0..8191
            const int row = f >> 6, c4 = f & 63;
            C4[(size_t)(3840 + row) * 2752 + 2688 + c4] = z;
        }
        return;
    }

    const int q = blockIdx.x / 59;
    const int r59 = blockIdx.x - q * 59;

    if (r59 < 43) {
        // ---------------- dequant W (block id = q*43 + r59) ----------------
        __shared__ float c[16];
        if (threadIdx.x < 16) c[threadIdx.x] = cent[threadIdx.x];
        __syncthreads();

        const int blk = q * 43 + r59;                  // 0 .. 22015
        const int idx = blk * 256 + threadIdx.x;       // 0 .. 11008*512-1
        const int o = idx >> 9;
        const int qq = idx & 511;
        const uint4 w = pw4[idx];
        const float norm = __ldg(&norms[o * 32 + (qq >> 4)]);

        __half2 h[4];
        h[0] = __floats2half2_rn(c[w.x & 15u] * norm, c[(w.x >> 4) & 15u] * norm);
        h[1] = __floats2half2_rn(c[w.y & 15u] * norm, c[(w.y >> 4) & 15u] * norm);
        h[2] = __floats2half2_rn(c[w.z & 15u] * norm, c[(w.z >> 4) & 15u] * norm);
        h[3] = __floats2half2_rn(c[w.w & 15u] * norm, c[(w.w >> 4) & 15u] * norm);

        const int nt = o >> 8, rr = o & 255;
        const int kc = qq >> 3;
        const uint32_t off = swz128((uint32_t)(rr * 128 + (qq & 7) * 16));
        const size_t base = ((size_t)nt * NKC + kc) * B_BLK_BYTES;
        *(uint4*)(Bt + base + off) = *(uint4*)h;
    } else {
        // ---------------- transform x (block id = q*16 + r59-43) ----------------
        const int blk = q * 16 + (r59 - 43);           // 0 .. 8191
        const int lane = threadIdx.x & 31;
        const int wrp = threadIdx.x >> 5;
        const int unit = blk * 8 + wrp;                // 0 .. 65535
        const int row = unit >> 4;
        const int g0 = (unit & 15) * 2;

        const float4 s1v = *(const float4*)(s1 + lane * 4);
        const float4 s2v = *(const float4*)(s2 + lane * 4);

        float v[8];
        {
            const float4 a = *(const float4*)(x + (size_t)row * K_DIM + g0 * GROUP + lane * 4);
            const float4 b = *(const float4*)(x + (size_t)row * K_DIM + (g0 + 1) * GROUP + lane * 4);
            v[0] = a.x * s1v.x; v[1] = a.y * s1v.y; v[2] = a.z * s1v.z; v[3] = a.w * s1v.w;
            v[4] = b.x * s1v.x; v[5] = b.y * s1v.y; v[6] = b.z * s1v.z; v[7] = b.w * s1v.w;
        }

#pragma unroll
        for (int pass = 0; pass < 2; pass++) {
#pragma unroll
            for (int h = 0; h < 2; h++) {
                float t0 = v[h*4+0] + v[h*4+1], t1 = v[h*4+0] - v[h*4+1];
                float t2 = v[h*4+2] + v[h*4+3], t3 = v[h*4+2] - v[h*4+3];
                v[h*4+0] = t0 + t2; v[h*4+2] = t0 - t2;
                v[h*4+1] = t1 + t3; v[h*4+3] = t1 - t3;
            }
#pragma unroll
            for (int xm = 1; xm <= 16; xm <<= 1) {
                bool hi = (lane & xm) != 0;
#pragma unroll
                for (int j = 0; j < 8; j++) {
                    float o = __shfl_xor_sync(0xFFFFFFFFu, v[j], xm);
                    v[j] = hi ? (o - v[j]) : (v[j] + o);
                }
            }
            if (pass == 0) {
                v[0] *= s2v.x; v[1] *= s2v.y; v[2] *= s2v.z; v[3] *= s2v.w;
                v[4] *= s2v.x; v[5] *= s2v.y; v[6] *= s2v.z; v[7] *= s2v.w;
            }
        }

        const float sc = 1.0f / 128.0f;
        const int mt = row >> 7, rr = row & 127;
        const int e = 4 * lane;
#pragma unroll
        for (int h = 0; h < 2; h++) {
            __half2 h01 = __floats2half2_rn(v[h*4+0] * sc, v[h*4+1] * sc);
            __half2 h23 = __floats2half2_rn(v[h*4+2] * sc, v[h*4+3] * sc);
            const int grp = g0 + h;
            const int kc = grp * 2 + (e >> 6);
            const int c = e & 63;
            const size_t base = ((size_t)mt * NKC + kc) * A_BLK_BYTES;
            const uint32_t off = swz128((uint32_t)(rr * 128 + c * 2));
            uint2 val = { *(uint32_t*)&h01, *(uint32_t*)&h23 };
            *(uint2*)(At + base + off) = val;
        }
    }
}

// ---------------------------------------------------------------------------
// Kernel 2: mma.sync GEMM. Mainloop FROZEN (byte-level identical schedule to
// the round-10 winner); only the chunk range [j0, j1) is parameterized with
// RELATIVE stage/parity indexing (j0=0 -> identical codegen). Tail pieces are
// full-N K-segments (22/21/21 chunks) with an atomicAdd epilogue into the
// pre-zeroed C region; segment 0 adds bias.
// ---------------------------------------------------------------------------
extern __shared__ unsigned char dsm[];

template <bool ATOMIC>
__device__ __forceinline__ void consume_tile(
    uint32_t sb, float* __restrict__ C, const float* __restrict__ bias,
    int bm, int bn, int wid, int lane, int j0, int j1) {
    const int wm = (wid >> 2) * 64;
    const int wn = (wid & 3) * 64;

    float acc[4][8][4];
#pragma unroll
    for (int i = 0; i < 4; i++)
#pragma unroll
        for (int j = 0; j < 8; j++)
#pragma unroll
            for (int k = 0; k < 4; k++) acc[i][j][k] = 0.0f;

    const int a_row = lane & 15;
    const int a_colh = (lane >> 4) * 8;
    const int b_row = (lane & 7) + (lane >> 4) * 8;
    const int b_colh = ((lane >> 3) & 1) * 8;

    const int nrel = j1 - j0;
    for (int rel = 0; rel < nrel; rel++) {
        const int s = rel & 3;
        MBAR_WAIT(sb + 8 * s, (rel >> 2) & 1);
        const uint32_t as = sb + 1024 + s * STAGE_BYTES;
        const uint32_t bs = as + A_BLK_BYTES;

#pragma unroll
        for (int ks = 0; ks < 4; ks++) {
            uint32_t afr[4][4];
#pragma unroll
            for (int m = 0; m < 4; m++)
                ldsm4(afr[m], as + swz128((uint32_t)((wm + m * 16 + a_row) * 128 +
                                                     (ks * 16 + a_colh) * 2)));
            uint32_t bfr[4][4];
#pragma unroll
            for (int nb = 0; nb < 4; nb++)
                ldsm4(bfr[nb], bs + swz128((uint32_t)((wn + nb * 16 + b_row) * 128 +
                                                      (ks * 16 + b_colh) * 2)));
#pragma unroll
            for (int m = 0; m < 4; m++) {
#pragma unroll
                for (int n = 0; n < 8; n++) {
                    mma16816(acc[m][n], afr[m], bfr[n >> 1][(n & 1) * 2],
                             bfr[n >> 1][(n & 1) * 2 + 1]);
                }
            }
        }
        if (lane == 0) MBAR_ARRIVE(sb + 32 + 8 * s);
    }

    // epilogue
    const int gid = lane >> 2;
    const int tq = lane & 3;
    float bz[8][2];
#pragma unroll
    for (int n = 0; n < 8; n++) {
        if (!ATOMIC || bias != nullptr) {
            const int col0 = bn + wn + n * 8 + tq * 2;
            bz[n][0] = __ldg(&bias[col0]);
            bz[n][1] = __ldg(&bias[col0 + 1]);
        } else {
            bz[n][0] = 0.0f;
            bz[n][1] = 0.0f;
        }
    }
#pragma unroll
    for (int m = 0; m < 4; m++) {
        const int row0 = bm + wm + m * 16 + gid;
#pragma unroll
        for (int n = 0; n < 8; n++) {
            const int col0 = bn + wn + n * 8 + tq * 2;
            const size_t o0 = (size_t)row0 * N_DIM + col0;
            const size_t o1 = (size_t)(row0 + 8) * N_DIM + col0;
            if (ATOMIC) {
                atomicAdd(C + o0,     acc[m][n][0] + bz[n][0]);
                atomicAdd(C + o0 + 1, acc[m][n][1] + bz[n][1]);
                atomicAdd(C + o1,     acc[m][n][2] + bz[n][0]);
                atomicAdd(C + o1 + 1, acc[m][n][3] + bz[n][1]);
            } else {
                float2 v0 = { acc[m][n][0] + bz[n][0], acc[m][n][1] + bz[n][1] };
                float2 v1 = { acc[m][n][2] + bz[n][0], acc[m][n][3] + bz[n][1] };
                *(float2*)(C + o0) = v0;
                *(float2*)(C + o1) = v1;
            }
        }
    }
}

__global__ __launch_bounds__(288, 1) void gemm_kernel(
    const unsigned char* __restrict__ At, const unsigned char* __restrict__ Bt,
    const float* __restrict__ bias, float* __restrict__ C) {
    const int tid = threadIdx.x;
    const int wid = tid >> 5;
    const int lane = tid & 31;
    const uint32_t sb = (smem_u32(dsm) + 1023) & ~1023u;

    // id -> (mt, nt, j0, j1). Full tiles: all 64 chunks. Tail tiles (last 44)
    // are K-split 3-way (22/21/21) at full N; segment 0 carries the bias.
    const int id = blockIdx.x;
    int mt, nt, j0, j1;
    bool tail;
    const float* bptr = bias;
    if (id < FULL_CTAS) {
        mt = id / NNT; nt = id - mt * NNT; j0 = 0; j1 = NKC; tail = false;
    } else {
        tail = true;
        const int p = id - FULL_CTAS;                 // 0..131
        const int t = FULL_CTAS + p / 3;              // 1332..1375
        const int seg = p - (p / 3) * 3;              // 0,1,2
        mt = t / NNT; nt = t - mt * NNT;
        j0 = (seg == 0) ? 0 : ((seg == 1) ? 22 : 43);
        j1 = (seg == 0) ? 22 : ((seg == 1) ? 43 : 64);
        if (seg != 0) bptr = nullptr;
    }
    const unsigned char* Ag = At + (size_t)mt * NKC * A_BLK_BYTES;
    const unsigned char* Bg = Bt + (size_t)nt * NKC * B_BLK_BYTES;
    const int bm = mt * BM;
    const int bn = nt * BN;

    if (tid == 0) {
#pragma unroll
        for (int s = 0; s < NSTAGES; s++) {
            MBAR_INIT(sb + 8 * s, 1);       // full[s]
            MBAR_INIT(sb + 32 + 8 * s, 8);  // empty[s]
        }
        asm volatile("fence.proxy.async.shared::cta;" ::: "memory");
    }
    __syncthreads();

    if (wid == 8) {
        // ---------------- producer warp (lane 0 only) ----------------
        if (lane == 0) {
            const int nrel = j1 - j0;
            for (int rel = 0; rel < nrel; rel++) {
                const int j = j0 + rel;               // absolute chunk
                const int s = rel & 3;
                if (rel >= NSTAGES) {
                    MBAR_WAIT(sb + 32 + 8 * s, ((rel >> 2) - 1) & 1);
                }
                const uint32_t full = sb + 8 * s;
                MBAR_EXPECT_TX(full, STAGE_BYTES);
                const uint32_t st = sb + 1024 + s * STAGE_BYTES;
                bulk_ld(st, Ag + (size_t)j * A_BLK_BYTES, A_BLK_BYTES, full);
                bulk_ld(st + A_BLK_BYTES, Bg + (size_t)j * B_BLK_BYTES, B_BLK_BYTES, full);
            }
        }
        return;
    }

    if (!tail) consume_tile<false>(sb, C, bias, bm, bn, wid, lane, 0, NKC);
    else       consume_tile<true>(sb, C, bptr, bm, bn, wid, lane, j0, j1);
}

// ---------------------------------------------------------------------------
// Launch (single stream): interleaved prep (+ tail-C zeroing), then GEMM.
// ---------------------------------------------------------------------------
extern "C" void kernel_launch(void* const* d_in, const int* in_sizes, int n_in,
                              void* d_out, int out_size) {
    const float* x     = (const float*)d_in[0];
    const uint4* pw4   = (const uint4*)d_in[1];
    const float* norms = (const float*)d_in[2];
    const float* cent  = (const float*)d_in[3];
    const float* s1    = (const float*)d_in[4];
    const float* s2v   = (const float*)d_in[5];
    const float* bias  = (const float*)d_in[6];
    float* out = (float*)d_out;

    unsigned char *At, *Bt;
    cudaGetSymbolAddress((void**)&At, g_A);
    cudaGetSymbolAddress((void**)&Bt, g_B);

    prep_kernel<<<PREP_TOTAL, 256>>>(x, s1, s2v, At, pw4, norms, cent, Bt, out);

    static bool attr_set = false;
    if (!attr_set) {
        cudaFuncSetAttribute(gemm_kernel, cudaFuncAttributeMaxDynamicSharedMemorySize,
                             SM_TOTAL);
        attr_set = true;
    }
    gemm_kernel<<<GRID_CTAS, 288, SM_TOTAL>>>(At, Bt, bias, out);
}